// round 6
// baseline (speedup 1.0000x reference)
#include <cuda_runtime.h>
#include <cstdint>

#define NSC   4
#define NTL   256
#define NMP   4096
#define HID   512
#define KNN   36
#define NJ    109         // 1 + 36 + 36 + 36
#define FEAT  130
#define NPAIR (NSC*NTL)

#define DCHUNK 13
#define NCHUNK 10
#define GEMM_THREADS 512

typedef unsigned long long u64;

// ---------------- scratch (no allocation allowed) ----------------
__device__ float g_rpe[NPAIR*72*3];     // per (s,i): 36 tt rel-poses then 36 tm rel-poses
__device__ int   g_idx_tm[NPAIR*KNN];   // selected map-token indices
__device__ int   g_benc;                // bool encoding: 0=uint8, 1=int32, 2=float32

// ---------------- glibc sinf/cosf emulation (optimized-routines) ----------------
#define GC_HPI_INV 0x1.45F306DC9C883p+23   // 2/pi * 2^24
#define GC_HPI     0x1.921FB54442D18p0     // pi/2 (double)
#define GC_S1    (-0x1.555545995720cp-3)
#define GC_S2    ( 0x1.1107605230bc4p-7)
#define GC_S3    (-0x1.994eb3774cf24p-13)
#define GC_C1    (-0x1.ffffffd0c5e81p-2)
#define GC_C2    ( 0x1.55553e1053a42p-5)
#define GC_C3    (-0x1.6c087e80f1e27p-10)
#define GC_C4    ( 0x1.99343027bf8c3p-16)

__device__ __forceinline__ float gl_poly(double x, double x2, int t, int odd){
    double r;
    if (!odd){
        double x3 = x * x2;
        double s1 = GC_S2 + x2 * GC_S3;
        double x7 = x3 * x2;
        double s  = x + x3 * GC_S1;
        r = s + x7 * s1;
    } else {
        double x4 = x2 * x2;
        double s2 = GC_C3 + x2 * GC_C4;
        double x6 = x4 * x2;
        double s1 = GC_C1 + x2 * GC_C2;
        double s  = 1.0 + x2 * s1;
        r = s + x6 * s2;
        if (t) r = -r;
    }
    return (float)r;
}

__device__ __forceinline__ float gl_sinf(float y){
    double x = (double)y;
    float ay = fabsf(y);
    if (ay < 0.75f){
        if (ay < 2.44140625e-4f) return y;
        return gl_poly(x, x*x, 0, 0);
    }
    double rr = x * GC_HPI_INV;
    int n = (((int)rr) + 0x800000) >> 24;
    double xr = fma((double)(-n), GC_HPI, x);
    double sg = ((n + 1) & 2) ? -1.0 : 1.0;
    int t = (n >> 1) & 1;
    return gl_poly(xr * sg, xr * xr, t, n & 1);
}

__device__ __forceinline__ float gl_cosf(float y){
    double x = (double)y;
    float ay = fabsf(y);
    if (ay < 0.75f){
        if (ay < 2.44140625e-4f) return 1.0f;
        return gl_poly(x, x*x, 0, 1);
    }
    double rr = x * GC_HPI_INV;
    int n = (((int)rr) + 0x800000) >> 24;
    double xr = fma((double)(-n), GC_HPI, x);
    int n1 = n + 1;
    double sg = ((n1 + 1) & 2) ? -1.0 : 1.0;
    int t = (n1 >> 1) & 1;
    return gl_poly(xr * sg, xr * xr, t, n1 & 1);
}

// ---------------- helpers ----------------
__device__ __forceinline__ float wrap_angle_f(float a){
    const float PI_F     = 3.14159265358979323846f;
    const float TWO_PI_F = 6.28318530717958647692f;
    float t = __fadd_rn(a, PI_F);
    float m = fmodf(t, TWO_PI_F);
    if (m < 0.f) m = __fadd_rn(m, TWO_PI_F);
    return __fsub_rn(m, PI_F);
}

__device__ __forceinline__ u64 dkey(float d, int j){
    return (((u64)__float_as_uint(d)) << 32) | (unsigned int)j;
}

__device__ __forceinline__ bool rbool(const void* p, int i){
    int e = g_benc;
    if (e == 1) return ((const int*)p)[i] != 0;
    if (e == 2) return ((const float*)p)[i] != 0.0f;
    return ((const unsigned char*)p)[i] != 0;
}

__device__ __forceinline__ void rel_pose_nf(float c, float sn,
                                            float dx, float dy,
                                            float& lx, float& ly){
    lx = __fadd_rn(__fmul_rn(c,  dx), __fmul_rn(sn, dy));
    ly = __fadd_rn(__fmul_rn(-sn, dx), __fmul_rn(c,  dy));
}
__device__ __forceinline__ float dist_nf(float dx, float dy){
    return sqrtf(__fadd_rn(__fmul_rn(dx,dx), __fmul_rn(dy,dy)));
}

__device__ __forceinline__ unsigned int smem_u32(const void* p){
    return (unsigned int)__cvta_generic_to_shared(p);
}
__device__ __forceinline__ void cp_async16(unsigned int dst, const void* src){
    asm volatile("cp.async.ca.shared.global [%0], [%1], 16;\n" :: "r"(dst), "l"(src));
}
__device__ __forceinline__ void cp_commit(){ asm volatile("cp.async.commit_group;\n"); }
__device__ __forceinline__ void cp_wait_1(){ asm volatile("cp.async.wait_group 1;\n"); }
__device__ __forceinline__ void cp_wait_0(){ asm volatile("cp.async.wait_group 0;\n"); }

__device__ __forceinline__ u64 pk2(float a, float b){
    u64 r;
    asm("mov.b64 %0, {%1, %2};" : "=l"(r) : "f"(a), "f"(b));
    return r;
}
__device__ __forceinline__ u64 fma2(u64 a, u64 b, u64 c){
    u64 d;
    asm("fma.rn.f32x2 %0, %1, %2, %3;" : "=l"(d) : "l"(a), "l"(b), "l"(c));
    return d;
}
__device__ __forceinline__ float2 up2(u64 v){
    float2 f;
    asm("mov.b64 {%0, %1}, %2;" : "=f"(f.x), "=f"(f.y) : "l"(v));
    return f;
}
__device__ __forceinline__ u64 u64min(u64 a, u64 b){ return a < b ? a : b; }
__device__ __forceinline__ u64 shfl_xor_u64(u64 v, int off){
    return __shfl_xor_sync(0xffffffffu, v, off);
}

// ---------------- kernel 0: detect bool encoding (1 warp) ----------------
__global__ void detect_bool_kernel(const unsigned int* __restrict__ p){
    int lane = threadIdx.x;
    bool okI = true, okF = true;
    #pragma unroll
    for (int q = 0; q < 8; q++){
        unsigned int w = p[lane*8 + q];
        if (w > 1u) okI = false;
        if (w != 0u && w != 0x3f800000u) okF = false;
    }
    unsigned bi = __ballot_sync(0xffffffffu, okI);
    unsigned bf = __ballot_sync(0xffffffffu, okF);
    if (lane == 0) g_benc = (bi == 0xffffffffu) ? 1 : ((bf == 0xffffffffu) ? 2 : 0);
}

// ---------------- kernel A: tl->tl KNN (register-resident, 1 key/thread) ----------------
__global__ void knn_tt_kernel(const void* __restrict__ tl_valid,
                              const float* __restrict__ tl_pose)
{
    __shared__ u64 wpart[8];
    __shared__ u64 mbc;
    __shared__ int sel[KNN];

    int pair = blockIdx.x;
    int s    = pair >> 8;
    int tid  = threadIdx.x;   // 256

    float sx = tl_pose[pair*3+0], sy = tl_pose[pair*3+1], syaw = tl_pose[pair*3+2];
    bool sinv = !rbool(tl_valid, pair);

    u64 vmin;
    {
        int j = tid;
        float tx = tl_pose[(s*NTL+j)*3+0], ty = tl_pose[(s*NTL+j)*3+1];
        float dx = __fsub_rn(tx, sx), dy = __fsub_rn(ty, sy);
        float dist = dist_nf(dx, dy);
        if (sinv || !rbool(tl_valid, s*NTL+j)) dist = 1e6f;
        vmin = dkey(dist, j);
    }

    int lane = tid & 31, wid = tid >> 5;
    for (int k = 0; k < KNN; k++){
        u64 v = vmin;
        #pragma unroll
        for (int off = 16; off; off >>= 1) v = u64min(v, shfl_xor_u64(v, off));
        if (lane == 0) wpart[wid] = v;
        __syncthreads();
        if (tid == 0){
            u64 m = wpart[0];
            #pragma unroll
            for (int w = 1; w < 8; w++) m = u64min(m, wpart[w]);
            mbc = m;
            sel[k] = (int)(m & 0xffffffffull);
        }
        __syncthreads();
        if (vmin == mbc) vmin = 0xffffffffffffffffull;   // owner retires its key
    }
    __syncthreads();

    if (tid < KNN){
        int ji = sel[tid];
        float c  = gl_cosf(syaw);
        float sn = gl_sinf(syaw);
        float tx = tl_pose[(s*NTL+ji)*3+0], ty = tl_pose[(s*NTL+ji)*3+1], tyaw = tl_pose[(s*NTL+ji)*3+2];
        float dx = __fsub_rn(tx, sx), dy = __fsub_rn(ty, sy);
        float lx, ly;
        rel_pose_nf(c, sn, dx, dy, lx, ly);
        float dyaw = wrap_angle_f(__fsub_rn(tyaw, syaw));
        int base = (pair*72 + tid)*3;
        g_rpe[base+0] = lx; g_rpe[base+1] = ly; g_rpe[base+2] = dyaw;
    }
}

// ---------------- kernel B: tl->mp KNN (register-resident, 8 keys/thread) ----------------
__global__ void knn_tm_kernel(const void* __restrict__ tl_valid,
                              const float* __restrict__ tl_pose,
                              const void* __restrict__ mp_invalid,
                              const float* __restrict__ mp_pose)
{
    __shared__ u64 wpart[16];
    __shared__ u64 mbc;
    __shared__ int sel[KNN];

    int pair = blockIdx.x;
    int s    = pair >> 8;
    int tid  = threadIdx.x;   // 512

    float sx = tl_pose[pair*3+0], sy = tl_pose[pair*3+1], syaw = tl_pose[pair*3+2];
    bool sinv = !rbool(tl_valid, pair);

    u64 keys[8];
    #pragma unroll
    for (int q = 0; q < 8; q++){
        int j = tid + q*512;
        float tx = mp_pose[(s*NMP+j)*3+0], ty = mp_pose[(s*NMP+j)*3+1];
        float dx = __fsub_rn(tx, sx), dy = __fsub_rn(ty, sy);
        float dist = dist_nf(dx, dy);
        if (sinv || rbool(mp_invalid, s*NMP+j)) dist = 1e6f;
        keys[q] = dkey(dist, j);
    }
    u64 vmin = keys[0];
    #pragma unroll
    for (int q = 1; q < 8; q++) vmin = u64min(vmin, keys[q]);

    int lane = tid & 31, wid = tid >> 5;
    for (int k = 0; k < KNN; k++){
        u64 v = vmin;
        #pragma unroll
        for (int off = 16; off; off >>= 1) v = u64min(v, shfl_xor_u64(v, off));
        if (lane == 0) wpart[wid] = v;
        __syncthreads();
        if (tid == 0){
            u64 m = wpart[0];
            #pragma unroll
            for (int w = 1; w < 16; w++) m = u64min(m, wpart[w]);
            mbc = m;
            sel[k] = (int)(m & 0xffffffffull);
        }
        __syncthreads();
        u64 m = mbc;
        if (vmin == m){   // owner: retire key, recompute local min
            #pragma unroll
            for (int q = 0; q < 8; q++)
                if (keys[q] == m) keys[q] = 0xffffffffffffffffull;
            vmin = keys[0];
            #pragma unroll
            for (int q = 1; q < 8; q++) vmin = u64min(vmin, keys[q]);
        }
    }
    __syncthreads();

    if (tid < KNN){
        int ji = sel[tid];
        float c  = gl_cosf(syaw);
        float sn = gl_sinf(syaw);
        float tx = mp_pose[(s*NMP+ji)*3+0], ty = mp_pose[(s*NMP+ji)*3+1], tyaw = mp_pose[(s*NMP+ji)*3+2];
        float dx = __fsub_rn(tx, sx), dy = __fsub_rn(ty, sy);
        float lx, ly;
        rel_pose_nf(c, sn, dx, dy, lx, ly);
        float dyaw = wrap_angle_f(__fsub_rn(tyaw, syaw));
        int base = (pair*72 + 36 + tid)*3;
        g_rpe[base+0] = lx; g_rpe[base+1] = ly; g_rpe[base+2] = dyaw;
        g_idx_tm[pair*KNN + tid] = ji;
    }
}

// ---------------- kernel C: feature gathers (j=0 and j=37..72) ----------------
__global__ void gather_copy_kernel(const int* __restrict__ tl_attr,
                                   const float* __restrict__ mp_feat,
                                   float* __restrict__ out)
{
    __shared__ int rows[37];
    int pair = blockIdx.x;
    int s    = pair >> 8;
    int tid  = threadIdx.x;   // 256

    if (tid == 0)        rows[0]   = tl_attr[pair];
    else if (tid < 37)   rows[tid] = g_idx_tm[pair*KNN + tid - 1];
    __syncthreads();

    const float4* src4 = (const float4*)mp_feat;
    float4*       out4 = (float4*)out;
    for (int q = tid; q < 37*128; q += 256){
        int rr = q >> 7;
        int w  = q & 127;
        int srow = rows[rr];
        int j = (rr == 0) ? 0 : (36 + rr);
        out4[((long)(pair*NJ + j))*128 + w] = src4[((long)(s*NMP + srow))*128 + w];
    }
}

// ---------------- kernel D: RPE embedding GEMM (72 x 130 x 512 per block) ----------------
// featT2: duplicated f32x2 features [130][72] u64 — broadcast operand arrives
// as one LDS.64, removing per-dd MOV packing. W double-buffered via cp.async.
__global__ void __launch_bounds__(GEMM_THREADS)
rpe_gemm_kernel(const float* __restrict__ W,
                const float* __restrict__ bvec,
                float* __restrict__ out)
{
    extern __shared__ char smch[];
    u64*   featT2 = (u64*)smch;                         // 130*72*8 = 74880 B
    float* wbuf   = (float*)(smch + FEAT*72*8);         // 2*13*512*4 = 53248 B
    __shared__ float rp[72][3];

    int pair = blockIdx.x;
    int tid  = threadIdx.x;

    if (tid < 216) rp[tid/3][tid%3] = g_rpe[pair*216 + tid];

    // prefetch W chunk 0 while features are computed
    {
        unsigned int wb0 = smem_u32(wbuf);
        const float* src = W;
        for (int q = tid; q < (DCHUNK*HID)/4; q += GEMM_THREADS)
            cp_async16(wb0 + q*16, src + q*4);
        cp_commit();
    }
    __syncthreads();   // rp ready

    for (int task = tid; task < 72*65; task += GEMM_THREADS){
        int r = task / 65;
        int t = task - r*65;
        if (t < 64){
            int isY = t >> 5;
            int f   = t & 31;
            float v   = rp[r][isY];
            float ang = v * __int_as_float((127 + f) << 23);  // exact *2^f
            float sv = sinf(ang), cv = cosf(ang);
            featT2[t*72 + r]        = pk2(sv, sv);
            featT2[(64 + t)*72 + r] = pk2(cv, cv);
        } else {
            float yv = rp[r][2];
            float cv = gl_cosf(yv), sv = gl_sinf(yv);
            featT2[128*72 + r] = pk2(cv, cv);
            featT2[129*72 + r] = pk2(sv, sv);
        }
    }

    int colt = tid & 63;        // 64 col tiles of 8
    int rowt = tid >> 6;        // 8 row tiles of 9
    int c0 = colt * 8;
    int r0 = rowt * 9;

    u64 acc[9][4];
    {
        const ulonglong2* bp = (const ulonglong2*)(bvec + c0);
        ulonglong2 bA = bp[0], bB = bp[1];
        #pragma unroll
        for (int r = 0; r < 9; r++){
            acc[r][0]=bA.x; acc[r][1]=bA.y; acc[r][2]=bB.x; acc[r][3]=bB.y;
        }
    }

    for (int ch = 0; ch < NCHUNK; ch++){
        if (ch + 1 < NCHUNK){
            unsigned int wb = smem_u32(wbuf + ((ch+1)&1)*DCHUNK*HID);
            const float* src = W + (ch+1)*DCHUNK*HID;
            for (int q = tid; q < (DCHUNK*HID)/4; q += GEMM_THREADS)
                cp_async16(wb + q*16, src + q*4);
            cp_commit();
            cp_wait_1();
        } else {
            cp_wait_0();
        }
        __syncthreads();   // chunk ch present; (iter 0) featT2 also ready

        const float* wbp = wbuf + (ch&1)*DCHUNK*HID;
        #pragma unroll 1
        for (int dd = 0; dd < DCHUNK; dd++){
            const u64* fb = featT2 + (ch*DCHUNK + dd)*72 + r0;
            const ulonglong2* wp = (const ulonglong2*)(wbp + dd*HID + c0);
            ulonglong2 wA = wp[0];       // cols c0..c0+3 packed
            ulonglong2 wB = wp[1];       // cols c0+4..c0+7 packed
            #pragma unroll
            for (int r = 0; r < 9; r++){
                u64 f = fb[r];
                acc[r][0] = fma2(f, wA.x, acc[r][0]);
                acc[r][1] = fma2(f, wA.y, acc[r][1]);
                acc[r][2] = fma2(f, wB.x, acc[r][2]);
                acc[r][3] = fma2(f, wB.y, acc[r][3]);
            }
        }
        __syncthreads();   // protect buffer before next chunk's cp.async overwrites
    }

    float4* out4 = (float4*)out;
    #pragma unroll
    for (int r = 0; r < 9; r++){
        int row = r0 + r;
        int j = (row < 36) ? (1 + row) : (37 + row);   // 1..36 (tt) / 73..108 (tm)
        float2 a = up2(acc[r][0]), b2 = up2(acc[r][1]);
        float2 c2 = up2(acc[r][2]), d2 = up2(acc[r][3]);
        long off = (((long)(pair*NJ + j))*HID + c0) >> 2;
        out4[off]   = make_float4(a.x, a.y, b2.x, b2.y);
        out4[off+1] = make_float4(c2.x, c2.y, d2.x, d2.y);
    }
}

// ---------------- host ----------------
extern "C" void kernel_launch(void* const* d_in, const int* in_sizes, int n_in,
                              void* d_out, int out_size)
{
    const void*          tl_valid   = d_in[0];
    const int*           tl_attr    = (const int*)d_in[1];
    const float*         tl_pose    = (const float*)d_in[2];
    const void*          mp_invalid = d_in[3];
    const float*         mp_feat    = (const float*)d_in[4];
    const float*         mp_pose    = (const float*)d_in[5];
    const float*         W          = (const float*)d_in[6];
    const float*         b          = (const float*)d_in[7];

    for (int i = 0; i < n_in; i++){
        int sz = in_sizes[i];
        if      (sz == NSC*NTL*3)    tl_pose    = (const float*)d_in[i];
        else if (sz == NSC*NMP)      mp_invalid = d_in[i];
        else if (sz == NSC*NMP*HID)  mp_feat    = (const float*)d_in[i];
        else if (sz == NSC*NMP*3)    mp_pose    = (const float*)d_in[i];
        else if (sz == FEAT*HID)     W          = (const float*)d_in[i];
        else if (sz == HID)          b          = (const float*)d_in[i];
    }

    float* out = (float*)d_out;
    (void)out_size;

    detect_bool_kernel<<<1, 32>>>((const unsigned int*)tl_valid);
    knn_tt_kernel<<<NPAIR, 256>>>(tl_valid, tl_pose);
    knn_tm_kernel<<<NPAIR, 512>>>(tl_valid, tl_pose, mp_invalid, mp_pose);
    gather_copy_kernel<<<NPAIR, 256>>>(tl_attr, mp_feat, out);

    size_t smem = (size_t)(FEAT*72*8 + 2*DCHUNK*HID*4);  // 74880 + 53248 = 128128 B
    cudaFuncSetAttribute(rpe_gemm_kernel,
                         cudaFuncAttributeMaxDynamicSharedMemorySize, (int)smem);
    rpe_gemm_kernel<<<NPAIR, GEMM_THREADS, smem>>>(W, b, out);
}

// round 7
// speedup vs baseline: 1.0750x; 1.0750x over previous
#include <cuda_runtime.h>
#include <cuda_bf16.h>
#include <cstdint>

#define NSC   4
#define NTL   256
#define NMP   4096
#define HID   512
#define KNN   36
#define NJ    109         // 1 + 36 + 36 + 36
#define FEAT  130
#define NPAIR (NSC*NTL)

#define KPAD  144         // 9 k-steps of 16
#define KSTR  152         // smem row stride in bf16 (bank-friendly: 304 B)
#define NBLK  256         // n-columns per GEMM block
#define GT    512

typedef unsigned long long u64;
typedef unsigned int u32;

// ---------------- scratch (no allocation allowed) ----------------
__device__ float g_rpe[NPAIR*72*3];     // per (s,i): 36 tt rel-poses then 36 tm rel-poses
__device__ int   g_idx_tm[NPAIR*KNN];   // selected map-token indices
__device__ int   g_benc;                // bool encoding: 0=uint8, 1=int32, 2=float32
__device__ __nv_bfloat16 g_wh[HID*KPAD];  // W^T hi [n][k]
__device__ __nv_bfloat16 g_wl[HID*KPAD];  // W^T lo [n][k]

// ---------------- glibc sinf/cosf emulation (optimized-routines) ----------------
#define GC_HPI_INV 0x1.45F306DC9C883p+23
#define GC_HPI     0x1.921FB54442D18p0
#define GC_S1    (-0x1.555545995720cp-3)
#define GC_S2    ( 0x1.1107605230bc4p-7)
#define GC_S3    (-0x1.994eb3774cf24p-13)
#define GC_C1    (-0x1.ffffffd0c5e81p-2)
#define GC_C2    ( 0x1.55553e1053a42p-5)
#define GC_C3    (-0x1.6c087e80f1e27p-10)
#define GC_C4    ( 0x1.99343027bf8c3p-16)

__device__ __forceinline__ float gl_poly(double x, double x2, int t, int odd){
    double r;
    if (!odd){
        double x3 = x * x2;
        double s1 = GC_S2 + x2 * GC_S3;
        double x7 = x3 * x2;
        double s  = x + x3 * GC_S1;
        r = s + x7 * s1;
    } else {
        double x4 = x2 * x2;
        double s2 = GC_C3 + x2 * GC_C4;
        double x6 = x4 * x2;
        double s1 = GC_C1 + x2 * GC_C2;
        double s  = 1.0 + x2 * s1;
        r = s + x6 * s2;
        if (t) r = -r;
    }
    return (float)r;
}

__device__ __forceinline__ float gl_sinf(float y){
    double x = (double)y;
    float ay = fabsf(y);
    if (ay < 0.75f){
        if (ay < 2.44140625e-4f) return y;
        return gl_poly(x, x*x, 0, 0);
    }
    double rr = x * GC_HPI_INV;
    int n = (((int)rr) + 0x800000) >> 24;
    double xr = fma((double)(-n), GC_HPI, x);
    double sg = ((n + 1) & 2) ? -1.0 : 1.0;
    int t = (n >> 1) & 1;
    return gl_poly(xr * sg, xr * xr, t, n & 1);
}

__device__ __forceinline__ float gl_cosf(float y){
    double x = (double)y;
    float ay = fabsf(y);
    if (ay < 0.75f){
        if (ay < 2.44140625e-4f) return 1.0f;
        return gl_poly(x, x*x, 0, 1);
    }
    double rr = x * GC_HPI_INV;
    int n = (((int)rr) + 0x800000) >> 24;
    double xr = fma((double)(-n), GC_HPI, x);
    int n1 = n + 1;
    double sg = ((n1 + 1) & 2) ? -1.0 : 1.0;
    int t = (n1 >> 1) & 1;
    return gl_poly(xr * sg, xr * xr, t, n1 & 1);
}

// ---------------- helpers ----------------
__device__ __forceinline__ float wrap_angle_f(float a){
    const float PI_F     = 3.14159265358979323846f;
    const float TWO_PI_F = 6.28318530717958647692f;
    float t = __fadd_rn(a, PI_F);
    float m = fmodf(t, TWO_PI_F);
    if (m < 0.f) m = __fadd_rn(m, TWO_PI_F);
    return __fsub_rn(m, PI_F);
}

__device__ __forceinline__ u64 dkey(float d, int j){
    return (((u64)__float_as_uint(d)) << 32) | (u32)j;
}

__device__ __forceinline__ bool rbool(const void* p, int i){
    int e = g_benc;
    if (e == 1) return ((const int*)p)[i] != 0;
    if (e == 2) return ((const float*)p)[i] != 0.0f;
    return ((const unsigned char*)p)[i] != 0;
}

__device__ __forceinline__ void rel_pose_nf(float c, float sn,
                                            float dx, float dy,
                                            float& lx, float& ly){
    lx = __fadd_rn(__fmul_rn(c,  dx), __fmul_rn(sn, dy));
    ly = __fadd_rn(__fmul_rn(-sn, dx), __fmul_rn(c,  dy));
}
__device__ __forceinline__ float dist_nf(float dx, float dy){
    return sqrtf(__fadd_rn(__fmul_rn(dx,dx), __fmul_rn(dy,dy)));
}

__device__ __forceinline__ u32 smem_u32(const void* p){
    return (u32)__cvta_generic_to_shared(p);
}
__device__ __forceinline__ void cp_async16(u32 dst, const void* src){
    asm volatile("cp.async.ca.shared.global [%0], [%1], 16;\n" :: "r"(dst), "l"(src));
}
__device__ __forceinline__ void cp_commit(){ asm volatile("cp.async.commit_group;\n"); }
__device__ __forceinline__ void cp_wait_0(){ asm volatile("cp.async.wait_group 0;\n"); }

__device__ __forceinline__ u64 u64min(u64 a, u64 b){ return a < b ? a : b; }
__device__ __forceinline__ u64 shfl_xor_u64(u64 v, int off){
    return __shfl_xor_sync(0xffffffffu, v, off);
}

__device__ __forceinline__ void ldsm_x4(u32& r0, u32& r1, u32& r2, u32& r3, u32 addr){
    asm volatile("ldmatrix.sync.aligned.m8n8.x4.shared.b16 {%0,%1,%2,%3},[%4];"
        : "=r"(r0), "=r"(r1), "=r"(r2), "=r"(r3) : "r"(addr));
}
__device__ __forceinline__ void ldsm_x2(u32& r0, u32& r1, u32 addr){
    asm volatile("ldmatrix.sync.aligned.m8n8.x2.shared.b16 {%0,%1},[%2];"
        : "=r"(r0), "=r"(r1) : "r"(addr));
}
__device__ __forceinline__ void mma16816(float& d0, float& d1, float& d2, float& d3,
                                         u32 a0, u32 a1, u32 a2, u32 a3,
                                         u32 b0, u32 b1){
    asm volatile("mma.sync.aligned.m16n8k16.row.col.f32.bf16.bf16.f32 "
        "{%0,%1,%2,%3},{%4,%5,%6,%7},{%8,%9},{%0,%1,%2,%3};"
        : "+f"(d0), "+f"(d1), "+f"(d2), "+f"(d3)
        : "r"(a0), "r"(a1), "r"(a2), "r"(a3), "r"(b0), "r"(b1));
}

// ---------------- kernel 0: detect bool encoding (1 warp) ----------------
__global__ void detect_bool_kernel(const u32* __restrict__ p){
    int lane = threadIdx.x;
    bool okI = true, okF = true;
    #pragma unroll
    for (int q = 0; q < 8; q++){
        u32 w = p[lane*8 + q];
        if (w > 1u) okI = false;
        if (w != 0u && w != 0x3f800000u) okF = false;
    }
    unsigned bi = __ballot_sync(0xffffffffu, okI);
    unsigned bf = __ballot_sync(0xffffffffu, okF);
    if (lane == 0) g_benc = (bi == 0xffffffffu) ? 1 : ((bf == 0xffffffffu) ? 2 : 0);
}

// ---------------- kernel W: split/transpose W into bf16 hi/lo ----------------
__global__ void prep_w_kernel(const float* __restrict__ W){
    int k = blockIdx.x;    // 0..143
    int n = threadIdx.x;   // 0..511
    float w = (k < FEAT) ? W[k*HID + n] : 0.0f;
    __nv_bfloat16 h = __float2bfloat16(w);
    float lo = w - __bfloat162float(h);
    g_wh[n*KPAD + k] = h;
    g_wl[n*KPAD + k] = __float2bfloat16(lo);
}

// ---------------- kernel A: tl->tl KNN (register-resident, 1 key/thread) ----------------
__global__ void knn_tt_kernel(const void* __restrict__ tl_valid,
                              const float* __restrict__ tl_pose)
{
    __shared__ u64 wpart[8];
    __shared__ u64 mbc;
    __shared__ int sel[KNN];

    int pair = blockIdx.x;
    int s    = pair >> 8;
    int tid  = threadIdx.x;   // 256

    float sx = tl_pose[pair*3+0], sy = tl_pose[pair*3+1], syaw = tl_pose[pair*3+2];
    bool sinv = !rbool(tl_valid, pair);

    u64 vmin;
    {
        int j = tid;
        float tx = tl_pose[(s*NTL+j)*3+0], ty = tl_pose[(s*NTL+j)*3+1];
        float dx = __fsub_rn(tx, sx), dy = __fsub_rn(ty, sy);
        float dist = dist_nf(dx, dy);
        if (sinv || !rbool(tl_valid, s*NTL+j)) dist = 1e6f;
        vmin = dkey(dist, j);
    }

    int lane = tid & 31, wid = tid >> 5;
    for (int k = 0; k < KNN; k++){
        u64 v = vmin;
        #pragma unroll
        for (int off = 16; off; off >>= 1) v = u64min(v, shfl_xor_u64(v, off));
        if (lane == 0) wpart[wid] = v;
        __syncthreads();
        if (tid == 0){
            u64 m = wpart[0];
            #pragma unroll
            for (int w = 1; w < 8; w++) m = u64min(m, wpart[w]);
            mbc = m;
            sel[k] = (int)(m & 0xffffffffull);
        }
        __syncthreads();
        if (vmin == mbc) vmin = 0xffffffffffffffffull;
    }
    __syncthreads();

    if (tid < KNN){
        int ji = sel[tid];
        float c  = gl_cosf(syaw);
        float sn = gl_sinf(syaw);
        float tx = tl_pose[(s*NTL+ji)*3+0], ty = tl_pose[(s*NTL+ji)*3+1], tyaw = tl_pose[(s*NTL+ji)*3+2];
        float dx = __fsub_rn(tx, sx), dy = __fsub_rn(ty, sy);
        float lx, ly;
        rel_pose_nf(c, sn, dx, dy, lx, ly);
        float dyaw = wrap_angle_f(__fsub_rn(tyaw, syaw));
        int base = (pair*72 + tid)*3;
        g_rpe[base+0] = lx; g_rpe[base+1] = ly; g_rpe[base+2] = dyaw;
    }
}

// ---------------- kernel B: tl->mp KNN (register-resident, 8 keys/thread) ----------------
__global__ void knn_tm_kernel(const void* __restrict__ tl_valid,
                              const float* __restrict__ tl_pose,
                              const void* __restrict__ mp_invalid,
                              const float* __restrict__ mp_pose)
{
    __shared__ u64 wpart[16];
    __shared__ u64 mbc;
    __shared__ int sel[KNN];

    int pair = blockIdx.x;
    int s    = pair >> 8;
    int tid  = threadIdx.x;   // 512

    float sx = tl_pose[pair*3+0], sy = tl_pose[pair*3+1], syaw = tl_pose[pair*3+2];
    bool sinv = !rbool(tl_valid, pair);

    u64 keys[8];
    #pragma unroll
    for (int q = 0; q < 8; q++){
        int j = tid + q*512;
        float tx = mp_pose[(s*NMP+j)*3+0], ty = mp_pose[(s*NMP+j)*3+1];
        float dx = __fsub_rn(tx, sx), dy = __fsub_rn(ty, sy);
        float dist = dist_nf(dx, dy);
        if (sinv || rbool(mp_invalid, s*NMP+j)) dist = 1e6f;
        keys[q] = dkey(dist, j);
    }
    u64 vmin = keys[0];
    #pragma unroll
    for (int q = 1; q < 8; q++) vmin = u64min(vmin, keys[q]);

    int lane = tid & 31, wid = tid >> 5;
    for (int k = 0; k < KNN; k++){
        u64 v = vmin;
        #pragma unroll
        for (int off = 16; off; off >>= 1) v = u64min(v, shfl_xor_u64(v, off));
        if (lane == 0) wpart[wid] = v;
        __syncthreads();
        if (tid == 0){
            u64 m = wpart[0];
            #pragma unroll
            for (int w = 1; w < 16; w++) m = u64min(m, wpart[w]);
            mbc = m;
            sel[k] = (int)(m & 0xffffffffull);
        }
        __syncthreads();
        u64 m = mbc;
        if (vmin == m){
            #pragma unroll
            for (int q = 0; q < 8; q++)
                if (keys[q] == m) keys[q] = 0xffffffffffffffffull;
            vmin = keys[0];
            #pragma unroll
            for (int q = 1; q < 8; q++) vmin = u64min(vmin, keys[q]);
        }
    }
    __syncthreads();

    if (tid < KNN){
        int ji = sel[tid];
        float c  = gl_cosf(syaw);
        float sn = gl_sinf(syaw);
        float tx = mp_pose[(s*NMP+ji)*3+0], ty = mp_pose[(s*NMP+ji)*3+1], tyaw = mp_pose[(s*NMP+ji)*3+2];
        float dx = __fsub_rn(tx, sx), dy = __fsub_rn(ty, sy);
        float lx, ly;
        rel_pose_nf(c, sn, dx, dy, lx, ly);
        float dyaw = wrap_angle_f(__fsub_rn(tyaw, syaw));
        int base = (pair*72 + 36 + tid)*3;
        g_rpe[base+0] = lx; g_rpe[base+1] = ly; g_rpe[base+2] = dyaw;
        g_idx_tm[pair*KNN + tid] = ji;
    }
}

// ---------------- kernel C: feature gathers (j=0 and j=37..72) ----------------
__global__ void gather_copy_kernel(const int* __restrict__ tl_attr,
                                   const float* __restrict__ mp_feat,
                                   float* __restrict__ out)
{
    __shared__ int rows[37];
    int pair = blockIdx.x;
    int s    = pair >> 8;
    int tid  = threadIdx.x;   // 256

    if (tid == 0)        rows[0]   = tl_attr[pair];
    else if (tid < 37)   rows[tid] = g_idx_tm[pair*KNN + tid - 1];
    __syncthreads();

    const float4* src4 = (const float4*)mp_feat;
    float4*       out4 = (float4*)out;
    for (int q = tid; q < 37*128; q += 256){
        int rr = q >> 7;
        int w  = q & 127;
        int srow = rows[rr];
        int j = (rr == 0) ? 0 : (36 + rr);
        out4[((long)(pair*NJ + j))*128 + w] = src4[((long)(s*NMP + srow))*128 + w];
    }
}

// ---------------- kernel D: RPE GEMM on tensor cores ----------------
// Block = (pair, n-half of 256). A = features split bf16 hi/lo in smem [80][152].
// W^T slice hi/lo staged via cp.async [256][152]. 3-product bf16 mma, f32 accum.
__global__ void __launch_bounds__(GT)
rpe_mma_kernel(const float* __restrict__ bvec, float* __restrict__ out)
{
    extern __shared__ char smch[];
    __nv_bfloat16* sAh = (__nv_bfloat16*)smch;           // [80][152]
    __nv_bfloat16* sAl = sAh + 80*KSTR;                  // [80][152]
    __nv_bfloat16* sWh = sAl + 80*KSTR;                  // [256][152]
    __nv_bfloat16* sWl = sWh + NBLK*KSTR;                // [256][152]
    __shared__ float rp[72][3];

    int pair = blockIdx.x >> 1;
    int nb   = blockIdx.x & 1;
    int tid  = threadIdx.x;

    // stage W slices (overlaps with feature compute)
    {
        int n0 = nb*NBLK;
        u32 dWh = smem_u32(sWh), dWl = smem_u32(sWl);
        for (int q = tid; q < NBLK*18; q += GT){
            int n = q / 18, c = q % 18;
            cp_async16(dWh + n*(KSTR*2) + c*16, g_wh + (n0+n)*KPAD + c*8);
        }
        for (int q = tid; q < NBLK*18; q += GT){
            int n = q / 18, c = q % 18;
            cp_async16(dWl + n*(KSTR*2) + c*16, g_wl + (n0+n)*KPAD + c*8);
        }
        cp_commit();
    }

    if (tid < 216) rp[tid/3][tid%3] = g_rpe[pair*216 + tid];

    // zero A (covers m 72..79 rows and k>=130 pad)
    {
        u32* z = (u32*)sAh;   // both arrays contiguous: 2*80*152 bf16 = 12160 u32
        for (int q = tid; q < 2*80*KSTR/2; q += GT) z[q] = 0u;
    }
    __syncthreads();   // rp ready, zero done

    // features -> bf16 hi/lo split
    for (int task = tid; task < 72*65; task += GT){
        int r = task / 65;
        int t = task - r*65;
        if (t < 64){
            int isY = t >> 5;
            int f   = t & 31;
            float v   = rp[r][isY];
            float ang = v * __int_as_float((127 + f) << 23);
            float sv = sinf(ang), cv = cosf(ang);
            __nv_bfloat16 sh = __float2bfloat16(sv);
            __nv_bfloat16 ch = __float2bfloat16(cv);
            sAh[r*KSTR + t]      = sh;
            sAl[r*KSTR + t]      = __float2bfloat16(sv - __bfloat162float(sh));
            sAh[r*KSTR + 64 + t] = ch;
            sAl[r*KSTR + 64 + t] = __float2bfloat16(cv - __bfloat162float(ch));
        } else {
            float yv = rp[r][2];
            float cv = gl_cosf(yv), sv = gl_sinf(yv);
            __nv_bfloat16 ch = __float2bfloat16(cv);
            __nv_bfloat16 sh = __float2bfloat16(sv);
            sAh[r*KSTR + 128] = ch;
            sAl[r*KSTR + 128] = __float2bfloat16(cv - __bfloat162float(ch));
            sAh[r*KSTR + 129] = sh;
            sAl[r*KSTR + 129] = __float2bfloat16(sv - __bfloat162float(sh));
        }
    }
    cp_wait_0();
    __syncthreads();

    // mainloop: warp w owns n16 (2 n-chunks), all 5 m-tiles
    int w = tid >> 5, l = tid & 31;
    int nw0 = w * 16;

    u32 aAh = smem_u32(sAh), aAl = smem_u32(sAl);
    u32 aWh = smem_u32(sWh), aWl = smem_u32(sWl);

    float acc[5][2][4];
    #pragma unroll
    for (int mt = 0; mt < 5; mt++)
        #pragma unroll
        for (int c = 0; c < 2; c++)
            #pragma unroll
            for (int i = 0; i < 4; i++) acc[mt][c][i] = 0.f;

    int lrow  = l & 15;          // A ldmatrix row lane
    int lkoff = (l >> 4) << 3;   // A ldmatrix k offset
    int brow  = l & 7;           // B ldmatrix row lane
    int bkoff = l & 8;           // B ldmatrix k offset

    #pragma unroll
    for (int ks = 0; ks < 9; ks++){
        int k0 = ks * 16;
        u32 bh0, bh1, bl0, bl1, bh2, bh3, bl2, bl3;
        ldsm_x2(bh0, bh1, aWh + ((nw0      + brow)*KSTR + k0 + bkoff)*2);
        ldsm_x2(bh2, bh3, aWh + ((nw0 + 8  + brow)*KSTR + k0 + bkoff)*2);
        ldsm_x2(bl0, bl1, aWl + ((nw0      + brow)*KSTR + k0 + bkoff)*2);
        ldsm_x2(bl2, bl3, aWl + ((nw0 + 8  + brow)*KSTR + k0 + bkoff)*2);
        #pragma unroll
        for (int mt = 0; mt < 5; mt++){
            u32 a0, a1, a2, a3, e0, e1, e2, e3;
            u32 aoff = ((mt*16 + lrow)*KSTR + k0 + lkoff)*2;
            ldsm_x4(a0, a1, a2, a3, aAh + aoff);
            ldsm_x4(e0, e1, e2, e3, aAl + aoff);
            mma16816(acc[mt][0][0], acc[mt][0][1], acc[mt][0][2], acc[mt][0][3],
                     a0, a1, a2, a3, bh0, bh1);
            mma16816(acc[mt][0][0], acc[mt][0][1], acc[mt][0][2], acc[mt][0][3],
                     a0, a1, a2, a3, bl0, bl1);
            mma16816(acc[mt][0][0], acc[mt][0][1], acc[mt][0][2], acc[mt][0][3],
                     e0, e1, e2, e3, bh0, bh1);
            mma16816(acc[mt][1][0], acc[mt][1][1], acc[mt][1][2], acc[mt][1][3],
                     a0, a1, a2, a3, bh2, bh3);
            mma16816(acc[mt][1][0], acc[mt][1][1], acc[mt][1][2], acc[mt][1][3],
                     a0, a1, a2, a3, bl2, bl3);
            mma16816(acc[mt][1][0], acc[mt][1][1], acc[mt][1][2], acc[mt][1][3],
                     e0, e1, e2, e3, bh2, bh3);
        }
    }

    // epilogue: add bias, scatter rows to j-slots
    #pragma unroll
    for (int c = 0; c < 2; c++){
        int n = nb*NBLK + nw0 + c*8 + 2*(l & 3);
        float bv0 = bvec[n], bv1 = bvec[n+1];
        #pragma unroll
        for (int mt = 0; mt < 5; mt++){
            int m = mt*16 + (l >> 2);
            {
                int j = (m < 36) ? (1 + m) : (37 + m);
                float2 v = make_float2(acc[mt][c][0] + bv0, acc[mt][c][1] + bv1);
                *(float2*)(out + ((long)(pair*NJ + j))*HID + n) = v;
            }
            int m2 = m + 8;
            if (m2 < 72){
                int j2 = (m2 < 36) ? (1 + m2) : (37 + m2);
                float2 v = make_float2(acc[mt][c][2] + bv0, acc[mt][c][3] + bv1);
                *(float2*)(out + ((long)(pair*NJ + j2))*HID + n) = v;
            }
        }
    }
}

// ---------------- host ----------------
extern "C" void kernel_launch(void* const* d_in, const int* in_sizes, int n_in,
                              void* d_out, int out_size)
{
    const void*          tl_valid   = d_in[0];
    const int*           tl_attr    = (const int*)d_in[1];
    const float*         tl_pose    = (const float*)d_in[2];
    const void*          mp_invalid = d_in[3];
    const float*         mp_feat    = (const float*)d_in[4];
    const float*         mp_pose    = (const float*)d_in[5];
    const float*         W          = (const float*)d_in[6];
    const float*         b          = (const float*)d_in[7];

    for (int i = 0; i < n_in; i++){
        int sz = in_sizes[i];
        if      (sz == NSC*NTL*3)    tl_pose    = (const float*)d_in[i];
        else if (sz == NSC*NMP)      mp_invalid = d_in[i];
        else if (sz == NSC*NMP*HID)  mp_feat    = (const float*)d_in[i];
        else if (sz == NSC*NMP*3)    mp_pose    = (const float*)d_in[i];
        else if (sz == FEAT*HID)     W          = (const float*)d_in[i];
        else if (sz == HID)          b          = (const float*)d_in[i];
    }

    float* out = (float*)d_out;
    (void)out_size;

    detect_bool_kernel<<<1, 32>>>((const u32*)tl_valid);
    prep_w_kernel<<<KPAD, HID>>>(W);
    knn_tt_kernel<<<NPAIR, 256>>>(tl_valid, tl_pose);
    knn_tm_kernel<<<NPAIR, 512>>>(tl_valid, tl_pose, mp_invalid, mp_pose);
    gather_copy_kernel<<<NPAIR, 256>>>(tl_attr, mp_feat, out);

    size_t smem = (size_t)(2*80*KSTR + 2*NBLK*KSTR) * sizeof(__nv_bfloat16); // 204,288 B
    cudaFuncSetAttribute(rpe_mma_kernel,
                         cudaFuncAttributeMaxDynamicSharedMemorySize, (int)smem);
    rpe_mma_kernel<<<NPAIR*2, GT, smem>>>(b, out);
}